// round 11
// baseline (speedup 1.0000x reference)
#include <cuda_runtime.h>
#include <stdint.h>

// x [n,c,h,w] fp32; per (n,c) row of hw=4096 keep top-k by |x|.
// out = x (kept) or x*(1-tau) (dropped).
// PERSISTENT grid: each CTA (256 thr) loops over rows, double-buffering the
// next row's loads in registers so DRAM streaming overlaps the barrier-heavy
// select phases. Select per row (key = bits<<1): 11-bit histogram (2048 bins)
// -> gather crossing class (<=256) -> 8-bit histogram over list -> gather
// subclass (<=64) -> 13-bit single-warp ballot search. Exact cold fallback.

constexpr int HW      = 4096;
constexpr int THREADS = 256;
constexpr int EPT     = HW / THREADS;    // 16
constexpr int NBIN    = 2048;
constexpr int BPT     = NBIN / THREADS;  // 8
constexpr int CAP1    = 256;
constexpr int CAP2    = 64;
constexpr int GRID    = 592;             // 148 SMs x 4 CTAs
constexpr unsigned FULL = 0xFFFFFFFFu;

__global__ __launch_bounds__(THREADS, 4)
void topk_blend_kernel(const float* __restrict__ x,
                       const float* __restrict__ tau_p,
                       const int*   __restrict__ k_p,
                       float*       __restrict__ out,
                       int rows)
{
    __shared__ uint32_t hist[NBIN];
    __shared__ uint32_t wtot[8];
    __shared__ uint32_t wtie[8];
    __shared__ uint32_t list1[CAP1];
    __shared__ uint32_t list2[CAP2];
    __shared__ uint32_t s_bin, s_krem, s_n1, s_n2, s_T, s_need, s_mode, s_cnt;

    const int tid  = threadIdx.x;
    const int wid  = tid >> 5;
    const int lane = tid & 31;

    const float tau = __ldg(tau_p);
    const int   K   = __ldg(k_p);
    const float omt = 1.0f - tau;
    const bool  sel = (K > 0 && K < HW);

    // zero hist once (scan phases re-zero it every iteration)
    reinterpret_cast<uint4*>(hist)[tid*2+0] = make_uint4(0,0,0,0);
    reinterpret_cast<uint4*>(hist)[tid*2+1] = make_uint4(0,0,0,0);
    __syncthreads();                                            // B1

    int row = blockIdx.x;
    if (row >= rows) return;

    // prologue: load first row
    uint32_t b[EPT];
    {
        const uint4* __restrict__ xin =
            reinterpret_cast<const uint4*>(x + (size_t)row * HW);
        #pragma unroll
        for (int i = 0; i < 4; i++) {
            uint4 v = xin[tid * 4 + i];
            b[i*4+0] = v.x; b[i*4+1] = v.y; b[i*4+2] = v.z; b[i*4+3] = v.w;
        }
    }

    while (true) {
        const int nrow = row + GRID;
        const bool have_next = (nrow < rows);

        // ---- issue next row's loads NOW; scoreboard-wait at the swap ----
        uint32_t bn[EPT];
        if (have_next) {
            const uint4* __restrict__ xin =
                reinterpret_cast<const uint4*>(x + (size_t)nrow * HW);
            #pragma unroll
            for (int i = 0; i < 4; i++) {
                uint4 v = xin[tid * 4 + i];
                bn[i*4+0] = v.x; bn[i*4+1] = v.y; bn[i*4+2] = v.z; bn[i*4+3] = v.w;
            }
        }

        // ================= SELECT on current row =================
        uint32_t T = 0, need = 0;
        int  t_excl = 0;
        bool geq = false;

        if (sel) {
            // ----- 11-bit histogram (key bits 31..21) -----
            #pragma unroll
            for (int j = 0; j < EPT; j++)
                atomicAdd(&hist[(b[j] >> 20) & 0x7FFu], 1u);
            __syncthreads();                                    // B2

            // ----- scan 2048 bins (8 per thread), self-zeroing -----
            {
                const int b0 = tid * BPT;
                uint4 h0 = reinterpret_cast<uint4*>(hist)[tid*2+0];
                uint4 h1 = reinterpret_cast<uint4*>(hist)[tid*2+1];
                reinterpret_cast<uint4*>(hist)[tid*2+0] = make_uint4(0,0,0,0);
                reinterpret_cast<uint4*>(hist)[tid*2+1] = make_uint4(0,0,0,0);
                uint32_t c[8] = {h0.x,h0.y,h0.z,h0.w,h1.x,h1.y,h1.z,h1.w};
                uint32_t suf[8];
                suf[7] = c[7];
                #pragma unroll
                for (int i = 6; i >= 0; i--) suf[i] = c[i] + suf[i+1];
                const uint32_t tot = suf[0];

                uint32_t s = tot;
                #pragma unroll
                for (int off = 1; off < 32; off <<= 1) {
                    uint32_t v = __shfl_down_sync(FULL, s, off);
                    if (lane + off < 32) s += v;
                }
                const uint32_t lane_hi = s - tot;
                if (lane == 0) wtot[wid] = s;
                __syncthreads();                                // B3

                uint32_t warp_hi = 0;
                #pragma unroll
                for (int w = 0; w < 8; w++) if (w > wid) warp_hi += wtot[w];
                const uint32_t off = lane_hi + warp_hi;
                const uint32_t Ku = (uint32_t)K;
                #pragma unroll
                for (int i = 0; i < 8; i++) {
                    uint32_t incl  = suf[i] + off;
                    uint32_t above = incl - c[i];
                    if (above < Ku && Ku <= incl) {
                        s_bin  = (uint32_t)(b0 + i);
                        s_krem = Ku - above;
                    }
                }
                if (tid == 0) s_n1 = 0;
            }
            __syncthreads();                                    // B4

            const uint32_t binsel = s_bin;
            const uint32_t krem1  = s_krem;

            // ----- gather crossing-class candidates -----
            #pragma unroll
            for (int j = 0; j < EPT; j++) {
                uint32_t key = b[j] << 1;
                if ((key >> 21) == binsel) {
                    uint32_t pos = atomicAdd(&s_n1, 1u);
                    if (pos < CAP1) list1[pos] = key & 0x1FFFFFu;
                }
            }
            __syncthreads();                                    // B5
            const uint32_t n1 = s_n1;

            if (n1 <= CAP1) {
                // ----- 8-bit histogram over the list (bits 20..13) -----
                for (uint32_t i = tid; i < n1; i += THREADS)
                    atomicAdd(&hist[(list1[i] >> 13) & 0xFFu], 1u);
                __syncthreads();                                // B6

                // ----- scan 256 bins -----
                {
                    uint32_t c2 = hist[tid];
                    hist[tid] = 0;
                    uint32_t s2 = c2;
                    #pragma unroll
                    for (int off = 1; off < 32; off <<= 1) {
                        uint32_t v = __shfl_down_sync(FULL, s2, off);
                        if (lane + off < 32) s2 += v;
                    }
                    if (lane == 0) wtot[wid] = s2;
                    __syncthreads();                            // B7
                    uint32_t hi2 = 0;
                    #pragma unroll
                    for (int w = 0; w < 8; w++) if (w > wid) hi2 += wtot[w];
                    uint32_t incl2  = s2 + hi2;
                    uint32_t above2 = incl2 - c2;
                    if (above2 < krem1 && krem1 <= incl2) {
                        s_bin  = (uint32_t)tid;
                        s_krem = krem1 - above2;
                    }
                    if (tid == 0) s_n2 = 0;
                }
                __syncthreads();                                // B8

                const uint32_t bin2  = s_bin;
                const uint32_t krem2 = s_krem;

                // ----- gather subclass -----
                for (uint32_t i = tid; i < n1; i += THREADS) {
                    uint32_t v = list1[i];
                    if (((v >> 13) & 0xFFu) == bin2) {
                        uint32_t pos = atomicAdd(&s_n2, 1u);
                        if (pos < CAP2) list2[pos] = v & 0x1FFFu;
                    }
                }
                __syncthreads();                                // B9
                const uint32_t n2 = s_n2;

                if (n2 <= CAP2) {
                    // ----- single-warp 13-bit ballot search -----
                    if (wid == 0) {
                        uint32_t cand[2]; bool val[2];
                        #pragma unroll
                        for (int i = 0; i < 2; i++) {
                            int idx = lane + 32 * i;
                            val[i]  = idx < (int)n2;
                            cand[i] = val[i] ? list2[idx] : 0u;
                        }
                        auto cnt_ge = [&](uint32_t t) -> uint32_t {
                            uint32_t n = 0;
                            #pragma unroll
                            for (int i = 0; i < 2; i++)
                                n += (uint32_t)__popc(__ballot_sync(FULL, val[i] && cand[i] >= t));
                            return n;
                        };
                        uint32_t v = 0;
                        #pragma unroll
                        for (int bit = 12; bit >= 0; bit--) {
                            uint32_t t = v | (1u << bit);
                            if (cnt_ge(t) >= krem2) v = t;
                        }
                        uint32_t n_gt = cnt_ge(v + 1);
                        uint32_t n_eq = cnt_ge(v) - n_gt;
                        uint32_t nd   = krem2 - n_gt;
                        if (lane == 0) {
                            s_T    = (binsel << 21) | (bin2 << 13) | v;
                            s_need = nd;
                            s_mode = (nd == n_eq) ? 1u : 0u;
                        }
                    }
                } else {
                    if (tid == 0) s_mode = 2u;
                }
                __syncthreads();                                // B10
            } else {
                if (tid == 0) s_mode = 2u;
                __syncthreads();                                // B10'
            }

            const uint32_t mode = s_mode;
            if (mode != 2u) {
                T    = s_T;
                need = s_need;
                geq  = (mode == 1u);
            } else {
                // ----- exact cold fallback: counting binary search -----
                uint32_t Tf = 0;
                const uint32_t Ku = (uint32_t)K;
                for (int bit = 30; bit >= 0; bit--) {
                    if (tid == 0) s_cnt = 0;
                    __syncthreads();
                    uint32_t trial = Tf | (1u << bit);
                    uint32_t cnt = 0;
                    #pragma unroll
                    for (int j = 0; j < EPT; j++) cnt += ((b[j] << 1) >= trial);
                    #pragma unroll
                    for (int off = 16; off >= 1; off >>= 1)
                        cnt += __shfl_down_sync(FULL, cnt, off);
                    if (lane == 0) atomicAdd(&s_cnt, cnt);
                    __syncthreads();
                    if (s_cnt >= Ku) Tf = trial;
                    __syncthreads();
                }
                uint32_t n_ge = 0, n_gt = 0;
                {
                    if (tid == 0) s_cnt = 0;
                    __syncthreads();
                    uint32_t cnt = 0;
                    #pragma unroll
                    for (int j = 0; j < EPT; j++) cnt += ((b[j] << 1) >= Tf);
                    #pragma unroll
                    for (int off = 16; off >= 1; off >>= 1)
                        cnt += __shfl_down_sync(FULL, cnt, off);
                    if (lane == 0) atomicAdd(&s_cnt, cnt);
                    __syncthreads();
                    n_ge = s_cnt;
                    __syncthreads();
                    if (tid == 0) s_cnt = 0;
                    __syncthreads();
                    cnt = 0;
                    #pragma unroll
                    for (int j = 0; j < EPT; j++) cnt += ((b[j] << 1) > Tf);
                    #pragma unroll
                    for (int off = 16; off >= 1; off >>= 1)
                        cnt += __shfl_down_sync(FULL, cnt, off);
                    if (lane == 0) atomicAdd(&s_cnt, cnt);
                    __syncthreads();
                    n_gt = s_cnt;
                }
                T    = Tf;
                need = Ku - n_gt;
                geq  = (need == (n_ge - n_gt));
            }

            // ----- stable tie rank (rare) -----
            if (!geq) {
                int myeq = 0;
                #pragma unroll
                for (int j = 0; j < EPT; j++) myeq += ((b[j] << 1) == T);
                uint32_t e = (uint32_t)myeq;
                #pragma unroll
                for (int off = 1; off < 32; off <<= 1) {
                    uint32_t v = __shfl_up_sync(FULL, e, off);
                    if (lane >= off) e += v;
                }
                if (lane == 31) wtie[wid] = e;
                __syncthreads();
                uint32_t lo = 0;
                #pragma unroll
                for (int w = 0; w < 8; w++) if (w < wid) lo += wtie[w];
                t_excl = (int)(e - (uint32_t)myeq + lo);
            }
        }

        // ================= APPLY current row =================
        {
            float4* __restrict__ yout =
                reinterpret_cast<float4*>(out + (size_t)row * HW);
            int rank = t_excl;
            const int needi = (int)need;
            #pragma unroll
            for (int i = 0; i < 4; i++) {
                float r[4];
                #pragma unroll
                for (int j = 0; j < 4; j++) {
                    const int idx = i * 4 + j;
                    uint32_t key = b[idx] << 1;
                    bool keep;
                    if (!sel)     keep = (K >= HW);
                    else if (geq) keep = (key >= T);
                    else {
                        keep = (key > T) | ((key == T) & (rank < needi));
                        rank += (key == T);
                    }
                    float xv = __uint_as_float(b[idx]);
                    r[j] = keep ? xv : xv * omt;
                }
                yout[tid * 4 + i] = make_float4(r[0], r[1], r[2], r[3]);
            }
        }

        if (!have_next) break;
        #pragma unroll
        for (int j = 0; j < EPT; j++) b[j] = bn[j];   // scoreboard wait here
        row = nrow;
    }
}

extern "C" void kernel_launch(void* const* d_in, const int* in_sizes, int n_in,
                              void* d_out, int out_size)
{
    const float* x   = (const float*)d_in[0];
    const float* tau = (const float*)d_in[1];
    const int*   k   = (const int*)d_in[2];
    float*       out = (float*)d_out;
    const int    rows = in_sizes[0] / HW;   // n*c = 8192

    const int grid = (rows < GRID) ? rows : GRID;
    topk_blend_kernel<<<grid, THREADS>>>(x, tau, k, out, rows);
}

// round 12
// speedup vs baseline: 1.2560x; 1.2560x over previous
#include <cuda_runtime.h>
#include <stdint.h>

// x [n,c,h,w] fp32; per (n,c) row of hw=4096 keep top-k by |x|.
// out = x (kept) or x*(1-tau) (dropped).
// Persistent CTAs (256 thr); next row prefetched into a double-buffered SMEM
// tile via cp.async so DRAM streaming overlaps the barrier-heavy select.
// Select per row (key = bits<<1): 11-bit histogram (2048 bins) -> gather
// crossing class (<=256) -> 8-bit histogram over the list -> gather subclass
// (<=64) -> 13-bit single-warp ballot search. Exact cold fallback + exact
// stable-tie path reading the row from SMEM in index order.

constexpr int HW      = 4096;
constexpr int THREADS = 256;
constexpr int EPT     = 16;
constexpr int NBIN    = 2048;
constexpr int BPT     = NBIN / THREADS;  // 8
constexpr int CAP1    = 256;
constexpr int CAP2    = 64;
constexpr int GRID    = 740;             // 148 SMs x 5 resident CTAs
constexpr unsigned FULL = 0xFFFFFFFFu;

__device__ __forceinline__ void cp16(uint32_t saddr, const void* gptr) {
    asm volatile("cp.async.cg.shared.global [%0], [%1], 16;"
                 :: "r"(saddr), "l"(gptr));
}
__device__ __forceinline__ void cp_commit() {
    asm volatile("cp.async.commit_group;");
}
template <int N>
__device__ __forceinline__ void cp_wait() {
    asm volatile("cp.async.wait_group %0;" :: "n"(N));
}

__global__ __launch_bounds__(THREADS, 5)
void topk_blend_kernel(const float* __restrict__ x,
                       const float* __restrict__ tau_p,
                       const int*   __restrict__ k_p,
                       float*       __restrict__ out,
                       int rows)
{
    __shared__ uint32_t buf[2][HW];      // 32 KB row double-buffer
    __shared__ uint32_t hist[NBIN];
    __shared__ uint32_t wtot[8];
    __shared__ uint32_t wtie[8];
    __shared__ uint32_t list1[CAP1];
    __shared__ uint32_t list2[CAP2];
    __shared__ uint32_t s_bin, s_krem, s_n1, s_n2, s_T, s_need, s_mode, s_cnt;

    const int tid  = threadIdx.x;
    const int wid  = tid >> 5;
    const int lane = tid & 31;

    const float tau = __ldg(tau_p);
    const int   K   = __ldg(k_p);
    const float omt = 1.0f - tau;
    const bool  sel = (K > 0 && K < HW);

    // zero hist once; select phases re-zero it each iteration
    reinterpret_cast<uint4*>(hist)[tid*2+0] = make_uint4(0,0,0,0);
    reinterpret_cast<uint4*>(hist)[tid*2+1] = make_uint4(0,0,0,0);
    __syncthreads();                                            // B1

    int row = blockIdx.x;
    if (row >= rows) return;

    uint32_t sbase[2];
    {
        uint32_t a;
        asm("{ .reg .u64 t; cvta.to.shared.u64 t, %1; cvt.u32.u64 %0, t; }"
            : "=r"(a) : "l"(&buf[0][0]));
        sbase[0] = a;
        sbase[1] = a + HW * 4;
    }

    // prologue: prefetch first row (thread t copies chunks t+256j)
    {
        const float* g = x + (size_t)row * HW;
        #pragma unroll
        for (int j = 0; j < 4; j++)
            cp16(sbase[0] + (uint32_t)(tid + 256*j) * 16, g + (tid + 256*j) * 4);
        cp_commit();
    }
    int cur = 0;

    while (true) {
        const int  nrow      = row + GRID;
        const bool have_next = (nrow < rows);

        if (have_next) {
            const float* g = x + (size_t)nrow * HW;
            #pragma unroll
            for (int j = 0; j < 4; j++)
                cp16(sbase[cur^1] + (uint32_t)(tid + 256*j) * 16, g + (tid + 256*j) * 4);
            cp_commit();
            cp_wait<1>();        // current row's group complete (per-thread)
        } else {
            cp_wait<0>();
        }

        // ---- copy own chunks smem -> regs (conflict-free LDS.128) ----
        uint32_t b[EPT];
        {
            const uint4* bu = reinterpret_cast<const uint4*>(&buf[cur][0]);
            #pragma unroll
            for (int j = 0; j < 4; j++) {
                uint4 v = bu[tid + 256*j];
                b[j*4+0] = v.x; b[j*4+1] = v.y; b[j*4+2] = v.z; b[j*4+3] = v.w;
            }
        }

        // ================= SELECT =================
        uint32_t T = 0, need = 0;
        bool geq = false;

        if (sel) {
            // ----- 11-bit histogram (key bits 31..21) -----
            #pragma unroll
            for (int j = 0; j < EPT; j++)
                atomicAdd(&hist[(b[j] >> 20) & 0x7FFu], 1u);
            __syncthreads();                                    // B2

            // ----- scan 2048 bins (8/thread), self-zeroing -----
            {
                const int b0 = tid * BPT;
                uint4 h0 = reinterpret_cast<uint4*>(hist)[tid*2+0];
                uint4 h1 = reinterpret_cast<uint4*>(hist)[tid*2+1];
                reinterpret_cast<uint4*>(hist)[tid*2+0] = make_uint4(0,0,0,0);
                reinterpret_cast<uint4*>(hist)[tid*2+1] = make_uint4(0,0,0,0);
                uint32_t c[8] = {h0.x,h0.y,h0.z,h0.w,h1.x,h1.y,h1.z,h1.w};
                uint32_t suf[8];
                suf[7] = c[7];
                #pragma unroll
                for (int i = 6; i >= 0; i--) suf[i] = c[i] + suf[i+1];
                const uint32_t tot = suf[0];

                uint32_t s = tot;
                #pragma unroll
                for (int off = 1; off < 32; off <<= 1) {
                    uint32_t v = __shfl_down_sync(FULL, s, off);
                    if (lane + off < 32) s += v;
                }
                const uint32_t lane_hi = s - tot;
                if (lane == 0) wtot[wid] = s;
                __syncthreads();                                // B3

                uint32_t warp_hi = 0;
                #pragma unroll
                for (int w = 0; w < 8; w++) if (w > wid) warp_hi += wtot[w];
                const uint32_t off = lane_hi + warp_hi;
                const uint32_t Ku = (uint32_t)K;
                #pragma unroll
                for (int i = 0; i < 8; i++) {
                    uint32_t incl  = suf[i] + off;
                    uint32_t above = incl - c[i];
                    if (above < Ku && Ku <= incl) {
                        s_bin  = (uint32_t)(b0 + i);
                        s_krem = Ku - above;
                    }
                }
                if (tid == 0) s_n1 = 0;
            }
            __syncthreads();                                    // B4

            const uint32_t binsel = s_bin;
            const uint32_t krem1  = s_krem;

            // ----- gather crossing-class candidates -----
            #pragma unroll
            for (int j = 0; j < EPT; j++) {
                uint32_t key = b[j] << 1;
                if ((key >> 21) == binsel) {
                    uint32_t pos = atomicAdd(&s_n1, 1u);
                    if (pos < CAP1) list1[pos] = key & 0x1FFFFFu;
                }
            }
            __syncthreads();                                    // B5
            const uint32_t n1 = s_n1;

            if (n1 <= CAP1) {
                // ----- 8-bit histogram over the list (bits 20..13) -----
                for (uint32_t i = tid; i < n1; i += THREADS)
                    atomicAdd(&hist[(list1[i] >> 13) & 0xFFu], 1u);
                __syncthreads();                                // B6

                // ----- scan 256 bins -----
                {
                    uint32_t c2 = hist[tid];
                    hist[tid] = 0;
                    uint32_t s2 = c2;
                    #pragma unroll
                    for (int off = 1; off < 32; off <<= 1) {
                        uint32_t v = __shfl_down_sync(FULL, s2, off);
                        if (lane + off < 32) s2 += v;
                    }
                    if (lane == 0) wtot[wid] = s2;
                    __syncthreads();                            // B7
                    uint32_t hi2 = 0;
                    #pragma unroll
                    for (int w = 0; w < 8; w++) if (w > wid) hi2 += wtot[w];
                    uint32_t incl2  = s2 + hi2;
                    uint32_t above2 = incl2 - c2;
                    if (above2 < krem1 && krem1 <= incl2) {
                        s_bin  = (uint32_t)tid;
                        s_krem = krem1 - above2;
                    }
                    if (tid == 0) s_n2 = 0;
                }
                __syncthreads();                                // B8

                const uint32_t bin2  = s_bin;
                const uint32_t krem2 = s_krem;

                // ----- gather subclass -----
                for (uint32_t i = tid; i < n1; i += THREADS) {
                    uint32_t v = list1[i];
                    if (((v >> 13) & 0xFFu) == bin2) {
                        uint32_t pos = atomicAdd(&s_n2, 1u);
                        if (pos < CAP2) list2[pos] = v & 0x1FFFu;
                    }
                }
                __syncthreads();                                // B9
                const uint32_t n2 = s_n2;

                if (n2 <= CAP2) {
                    // ----- single-warp 13-bit ballot search -----
                    if (wid == 0) {
                        uint32_t cand[2]; bool val[2];
                        #pragma unroll
                        for (int i = 0; i < 2; i++) {
                            int idx = lane + 32 * i;
                            val[i]  = idx < (int)n2;
                            cand[i] = val[i] ? list2[idx] : 0u;
                        }
                        auto cnt_ge = [&](uint32_t t) -> uint32_t {
                            uint32_t n = 0;
                            #pragma unroll
                            for (int i = 0; i < 2; i++)
                                n += (uint32_t)__popc(__ballot_sync(FULL, val[i] && cand[i] >= t));
                            return n;
                        };
                        uint32_t v = 0;
                        #pragma unroll
                        for (int bit = 12; bit >= 0; bit--) {
                            uint32_t t = v | (1u << bit);
                            if (cnt_ge(t) >= krem2) v = t;
                        }
                        uint32_t n_gt = cnt_ge(v + 1);
                        uint32_t n_eq = cnt_ge(v) - n_gt;
                        uint32_t nd   = krem2 - n_gt;
                        if (lane == 0) {
                            s_T    = (binsel << 21) | (bin2 << 13) | v;
                            s_need = nd;
                            s_mode = (nd == n_eq) ? 1u : 0u;
                        }
                    }
                } else {
                    if (tid == 0) s_mode = 2u;
                }
                __syncthreads();                                // B10
            } else {
                if (tid == 0) s_mode = 2u;
                __syncthreads();                                // B10'
            }

            const uint32_t mode = s_mode;
            if (mode != 2u) {
                T    = s_T;
                need = s_need;
                geq  = (mode == 1u);
            } else {
                // ----- exact cold fallback: counting binary search -----
                uint32_t Tf = 0;
                const uint32_t Ku = (uint32_t)K;
                for (int bit = 30; bit >= 0; bit--) {
                    if (tid == 0) s_cnt = 0;
                    __syncthreads();
                    uint32_t trial = Tf | (1u << bit);
                    uint32_t cnt = 0;
                    #pragma unroll
                    for (int j = 0; j < EPT; j++) cnt += ((b[j] << 1) >= trial);
                    #pragma unroll
                    for (int off = 16; off >= 1; off >>= 1)
                        cnt += __shfl_down_sync(FULL, cnt, off);
                    if (lane == 0) atomicAdd(&s_cnt, cnt);
                    __syncthreads();
                    if (s_cnt >= Ku) Tf = trial;
                    __syncthreads();
                }
                uint32_t n_ge = 0, n_gt = 0;
                {
                    if (tid == 0) s_cnt = 0;
                    __syncthreads();
                    uint32_t cnt = 0;
                    #pragma unroll
                    for (int j = 0; j < EPT; j++) cnt += ((b[j] << 1) >= Tf);
                    #pragma unroll
                    for (int off = 16; off >= 1; off >>= 1)
                        cnt += __shfl_down_sync(FULL, cnt, off);
                    if (lane == 0) atomicAdd(&s_cnt, cnt);
                    __syncthreads();
                    n_ge = s_cnt;
                    __syncthreads();
                    if (tid == 0) s_cnt = 0;
                    __syncthreads();
                    cnt = 0;
                    #pragma unroll
                    for (int j = 0; j < EPT; j++) cnt += ((b[j] << 1) > Tf);
                    #pragma unroll
                    for (int off = 16; off >= 1; off >>= 1)
                        cnt += __shfl_down_sync(FULL, cnt, off);
                    if (lane == 0) atomicAdd(&s_cnt, cnt);
                    __syncthreads();
                    n_gt = s_cnt;
                }
                T    = Tf;
                need = Ku - n_gt;
                geq  = (need == (n_ge - n_gt));
            }
        }

        // ================= APPLY =================
        if (!sel || geq) {
            // common path: from registers, strided coalesced stores
            const bool keepall = (K >= HW);
            float4* __restrict__ yout =
                reinterpret_cast<float4*>(out + (size_t)row * HW);
            #pragma unroll
            for (int j = 0; j < 4; j++) {
                float r[4];
                #pragma unroll
                for (int q = 0; q < 4; q++) {
                    const int idx = j * 4 + q;
                    float xv = __uint_as_float(b[idx]);
                    bool keep = sel ? ((b[idx] << 1) >= T) : keepall;
                    r[q] = keep ? xv : xv * omt;
                }
                yout[tid + 256*j] = make_float4(r[0], r[1], r[2], r[3]);
            }
        } else {
            // rare tie path: exact stable ranks require index order.
            // Read pristine row from SMEM in blocked layout.
            const uint32_t* bu = &buf[cur][0];
            int myeq = 0;
            #pragma unroll
            for (int j = 0; j < EPT; j++)
                myeq += ((bu[tid*16 + j] << 1) == T);
            uint32_t e = (uint32_t)myeq;
            #pragma unroll
            for (int off = 1; off < 32; off <<= 1) {
                uint32_t v = __shfl_up_sync(FULL, e, off);
                if (lane >= off) e += v;
            }
            if (lane == 31) wtie[wid] = e;
            __syncthreads();
            uint32_t lo = 0;
            #pragma unroll
            for (int w = 0; w < 8; w++) if (w < wid) lo += wtie[w];
            int rank = (int)(e - (uint32_t)myeq + lo);

            const int needi = (int)need;
            float4* __restrict__ yout =
                reinterpret_cast<float4*>(out + (size_t)row * HW);
            #pragma unroll
            for (int i = 0; i < 4; i++) {
                float r[4];
                #pragma unroll
                for (int q = 0; q < 4; q++) {
                    uint32_t bits = bu[tid*16 + i*4 + q];
                    uint32_t key  = bits << 1;
                    bool keep = (key > T) | ((key == T) & (rank < needi));
                    rank += (key == T);
                    float xv = __uint_as_float(bits);
                    r[q] = keep ? xv : xv * omt;
                }
                yout[tid*4 + i] = make_float4(r[0], r[1], r[2], r[3]);
            }
            __syncthreads();   // protect buf[cur] from next iteration's prefetch
        }

        if (!have_next) break;
        cur ^= 1;
        row = nrow;
    }
}

extern "C" void kernel_launch(void* const* d_in, const int* in_sizes, int n_in,
                              void* d_out, int out_size)
{
    const float* x   = (const float*)d_in[0];
    const float* tau = (const float*)d_in[1];
    const int*   k   = (const int*)d_in[2];
    float*       out = (float*)d_out;
    const int    rows = in_sizes[0] / HW;   // n*c = 8192

    const int grid = (rows < GRID) ? rows : GRID;
    topk_blend_kernel<<<grid, THREADS>>>(x, tau, k, out, rows);
}

// round 13
// speedup vs baseline: 1.2960x; 1.0319x over previous
#include <cuda_runtime.h>
#include <stdint.h>

// x [n,c,h,w] fp32; per (n,c) row of hw=4096 keep top-k by |x|.
// out = x (kept) or x*(1-tau) (dropped).
// Persistent CTAs (256 thr); next row prefetched into a double-buffered SMEM
// tile via cp.async so DRAM streaming overlaps the barrier-heavy select.
// Select per row (key = bits<<1): 11-bit histogram (2048 bins) -> fused
// gather+8-bit histogram of the crossing class (<=256) -> ONE warp scans the
// 256 bins, compacts the subclass and ballot-searches the last 13 bits.
// 5 block barriers per row on the common path. Exact cold fallback + exact
// stable-tie path reading the row from SMEM in index order.

constexpr int HW      = 4096;
constexpr int THREADS = 256;
constexpr int EPT     = 16;
constexpr int NBIN    = 2048;
constexpr int BPT     = NBIN / THREADS;  // 8
constexpr int CAP1    = 256;
constexpr int CAP2    = 64;
constexpr int GRID    = 740;             // 148 SMs x 5 resident CTAs
constexpr unsigned FULL = 0xFFFFFFFFu;

__device__ __forceinline__ void cp16(uint32_t saddr, const void* gptr) {
    asm volatile("cp.async.cg.shared.global [%0], [%1], 16;"
                 :: "r"(saddr), "l"(gptr));
}
__device__ __forceinline__ void cp_commit() {
    asm volatile("cp.async.commit_group;");
}
template <int N>
__device__ __forceinline__ void cp_wait() {
    asm volatile("cp.async.wait_group %0;" :: "n"(N));
}

__global__ __launch_bounds__(THREADS, 5)
void topk_blend_kernel(const float* __restrict__ x,
                       const float* __restrict__ tau_p,
                       const int*   __restrict__ k_p,
                       float*       __restrict__ out,
                       int rows)
{
    __shared__ uint32_t buf[2][HW];      // 32 KB row double-buffer
    __shared__ uint32_t hist[NBIN];
    __shared__ uint32_t wtot[8];
    __shared__ uint32_t wtie[8];
    __shared__ uint32_t list1[CAP1];
    __shared__ uint32_t list2[CAP2];
    __shared__ uint32_t s_bin, s_krem, s_n1, s_T, s_need, s_mode, s_cnt;

    const int tid  = threadIdx.x;
    const int wid  = tid >> 5;
    const int lane = tid & 31;

    const float tau = __ldg(tau_p);
    const int   K   = __ldg(k_p);
    const float omt = 1.0f - tau;
    const bool  sel = (K > 0 && K < HW);

    // zero hist once; select phases keep it zeroed iteration-to-iteration
    reinterpret_cast<uint4*>(hist)[tid*2+0] = make_uint4(0,0,0,0);
    reinterpret_cast<uint4*>(hist)[tid*2+1] = make_uint4(0,0,0,0);
    __syncthreads();

    int row = blockIdx.x;
    if (row >= rows) return;

    uint32_t sbase[2];
    {
        uint32_t a;
        asm("{ .reg .u64 t; cvta.to.shared.u64 t, %1; cvt.u32.u64 %0, t; }"
            : "=r"(a) : "l"(&buf[0][0]));
        sbase[0] = a;
        sbase[1] = a + HW * 4;
    }

    // prologue: prefetch first row (thread t owns 16B chunks t+256j)
    {
        const float* g = x + (size_t)row * HW;
        #pragma unroll
        for (int j = 0; j < 4; j++)
            cp16(sbase[0] + (uint32_t)(tid + 256*j) * 16, g + (tid + 256*j) * 4);
        cp_commit();
    }
    int cur = 0;

    while (true) {
        const int  nrow      = row + GRID;
        const bool have_next = (nrow < rows);

        if (have_next) {
            const float* g = x + (size_t)nrow * HW;
            #pragma unroll
            for (int j = 0; j < 4; j++)
                cp16(sbase[cur^1] + (uint32_t)(tid + 256*j) * 16, g + (tid + 256*j) * 4);
            cp_commit();
            cp_wait<1>();        // current row's group complete
        } else {
            cp_wait<0>();
        }

        // ---- own chunks smem -> regs (conflict-free LDS.128) ----
        uint32_t b[EPT];
        {
            const uint4* bu = reinterpret_cast<const uint4*>(&buf[cur][0]);
            #pragma unroll
            for (int j = 0; j < 4; j++) {
                uint4 v = bu[tid + 256*j];
                b[j*4+0] = v.x; b[j*4+1] = v.y; b[j*4+2] = v.z; b[j*4+3] = v.w;
            }
        }

        // ================= SELECT =================
        uint32_t T = 0, need = 0;
        bool geq = false;

        if (sel) {
            // ----- 11-bit histogram (key bits 31..21) -----
            #pragma unroll
            for (int j = 0; j < EPT; j++)
                atomicAdd(&hist[(b[j] >> 20) & 0x7FFu], 1u);
            __syncthreads();                                    // B2

            // ----- scan 2048 bins (8/thread), self-zeroing -----
            {
                const int b0 = tid * BPT;
                uint4 h0 = reinterpret_cast<uint4*>(hist)[tid*2+0];
                uint4 h1 = reinterpret_cast<uint4*>(hist)[tid*2+1];
                reinterpret_cast<uint4*>(hist)[tid*2+0] = make_uint4(0,0,0,0);
                reinterpret_cast<uint4*>(hist)[tid*2+1] = make_uint4(0,0,0,0);
                uint32_t c[8] = {h0.x,h0.y,h0.z,h0.w,h1.x,h1.y,h1.z,h1.w};
                uint32_t suf[8];
                suf[7] = c[7];
                #pragma unroll
                for (int i = 6; i >= 0; i--) suf[i] = c[i] + suf[i+1];
                const uint32_t tot = suf[0];

                uint32_t s = tot;
                #pragma unroll
                for (int off = 1; off < 32; off <<= 1) {
                    uint32_t v = __shfl_down_sync(FULL, s, off);
                    if (lane + off < 32) s += v;
                }
                const uint32_t lane_hi = s - tot;
                if (lane == 0) wtot[wid] = s;
                __syncthreads();                                // B3

                uint32_t warp_hi = 0;
                #pragma unroll
                for (int w = 0; w < 8; w++) if (w > wid) warp_hi += wtot[w];
                const uint32_t off = lane_hi + warp_hi;
                const uint32_t Ku = (uint32_t)K;
                #pragma unroll
                for (int i = 0; i < 8; i++) {
                    uint32_t incl  = suf[i] + off;
                    uint32_t above = incl - c[i];
                    if (above < Ku && Ku <= incl) {
                        s_bin  = (uint32_t)(b0 + i);
                        s_krem = Ku - above;
                    }
                }
                if (tid == 0) s_n1 = 0;
            }
            __syncthreads();                                    // B4

            const uint32_t binsel = s_bin;
            const uint32_t krem1  = s_krem;

            // ----- fused gather + 8-bit histogram (bits 20..13) -----
            #pragma unroll
            for (int j = 0; j < EPT; j++) {
                uint32_t key = b[j] << 1;
                if ((key >> 21) == binsel) {
                    uint32_t rem = key & 0x1FFFFFu;
                    uint32_t pos = atomicAdd(&s_n1, 1u);
                    if (pos < CAP1) list1[pos] = rem;
                    atomicAdd(&hist[rem >> 13], 1u);
                }
            }
            __syncthreads();                                    // B5
            const uint32_t n1 = s_n1;

            // ----- single-warp: scan 256 bins, compact subclass, search ----
            if (wid == 0) {
                // read + zero bins 0..255 (8 blocked per lane) — always, so
                // hist stays zeroed even on the fallback path
                uint4 h0 = reinterpret_cast<uint4*>(hist)[lane*2+0];
                uint4 h1 = reinterpret_cast<uint4*>(hist)[lane*2+1];
                reinterpret_cast<uint4*>(hist)[lane*2+0] = make_uint4(0,0,0,0);
                reinterpret_cast<uint4*>(hist)[lane*2+1] = make_uint4(0,0,0,0);

                if (n1 <= CAP1) {
                    uint32_t c[8] = {h0.x,h0.y,h0.z,h0.w,h1.x,h1.y,h1.z,h1.w};
                    uint32_t suf[8];
                    suf[7] = c[7];
                    #pragma unroll
                    for (int i = 6; i >= 0; i--) suf[i] = c[i] + suf[i+1];
                    const uint32_t tot = suf[0];
                    uint32_t s = tot;
                    #pragma unroll
                    for (int off = 1; off < 32; off <<= 1) {
                        uint32_t v = __shfl_down_sync(FULL, s, off);
                        if (lane + off < 32) s += v;
                    }
                    const uint32_t lane_hi = s - tot;

                    uint32_t bin2 = 0, krem2 = 0;
                    bool found = false;
                    #pragma unroll
                    for (int i = 0; i < 8; i++) {
                        uint32_t incl  = suf[i] + lane_hi;
                        uint32_t above = incl - c[i];
                        if (above < krem1 && krem1 <= incl) {
                            found = true;
                            bin2  = (uint32_t)(lane * 8 + i);
                            krem2 = krem1 - above;
                        }
                    }
                    unsigned fm = __ballot_sync(FULL, found);
                    int src = __ffs(fm) - 1;
                    bin2  = __shfl_sync(FULL, bin2,  src);
                    krem2 = __shfl_sync(FULL, krem2, src);

                    // compact subclass candidates into list2 (ballot prefix)
                    uint32_t nout = 0;
                    #pragma unroll
                    for (int i = 0; i < 8; i++) {
                        int idx = lane + 32 * i;
                        uint32_t v = (idx < (int)n1) ? list1[idx] : 0u;
                        bool m = (idx < (int)n1) && ((v >> 13) == bin2);
                        unsigned mm = __ballot_sync(FULL, m);
                        if (m) {
                            int pos = (int)nout + __popc(mm & ((1u << lane) - 1u));
                            if (pos < CAP2) list2[pos] = v & 0x1FFFu;
                        }
                        nout += (uint32_t)__popc(mm);
                    }

                    if (nout <= CAP2) {
                        // 13-bit ballot binary search, 2 candidates/lane
                        uint32_t cand[2]; bool val[2];
                        #pragma unroll
                        for (int i = 0; i < 2; i++) {
                            int idx = lane + 32 * i;
                            val[i]  = idx < (int)nout;
                            cand[i] = val[i] ? list2[idx] : 0u;
                        }
                        auto cnt_ge = [&](uint32_t t) -> uint32_t {
                            uint32_t n = 0;
                            #pragma unroll
                            for (int i = 0; i < 2; i++)
                                n += (uint32_t)__popc(__ballot_sync(FULL, val[i] && cand[i] >= t));
                            return n;
                        };
                        uint32_t v = 0;
                        #pragma unroll
                        for (int bit = 12; bit >= 0; bit--) {
                            uint32_t t = v | (1u << bit);
                            if (cnt_ge(t) >= krem2) v = t;
                        }
                        uint32_t n_gt = cnt_ge(v + 1);
                        uint32_t n_eq = cnt_ge(v) - n_gt;
                        uint32_t nd   = krem2 - n_gt;
                        if (lane == 0) {
                            s_T    = (binsel << 21) | (bin2 << 13) | v;
                            s_need = nd;
                            s_mode = (nd == n_eq) ? 1u : 0u;
                        }
                    } else if (lane == 0) {
                        s_mode = 2u;
                    }
                } else if (lane == 0) {
                    s_mode = 2u;
                }
            }
            __syncthreads();                                    // B6

            const uint32_t mode = s_mode;
            if (mode != 2u) {
                T    = s_T;
                need = s_need;
                geq  = (mode == 1u);
            } else {
                // ----- exact cold fallback: counting binary search -----
                uint32_t Tf = 0;
                const uint32_t Ku = (uint32_t)K;
                for (int bit = 30; bit >= 0; bit--) {
                    if (tid == 0) s_cnt = 0;
                    __syncthreads();
                    uint32_t trial = Tf | (1u << bit);
                    uint32_t cnt = 0;
                    #pragma unroll
                    for (int j = 0; j < EPT; j++) cnt += ((b[j] << 1) >= trial);
                    #pragma unroll
                    for (int off = 16; off >= 1; off >>= 1)
                        cnt += __shfl_down_sync(FULL, cnt, off);
                    if (lane == 0) atomicAdd(&s_cnt, cnt);
                    __syncthreads();
                    if (s_cnt >= Ku) Tf = trial;
                    __syncthreads();
                }
                uint32_t n_ge = 0, n_gt = 0;
                {
                    if (tid == 0) s_cnt = 0;
                    __syncthreads();
                    uint32_t cnt = 0;
                    #pragma unroll
                    for (int j = 0; j < EPT; j++) cnt += ((b[j] << 1) >= Tf);
                    #pragma unroll
                    for (int off = 16; off >= 1; off >>= 1)
                        cnt += __shfl_down_sync(FULL, cnt, off);
                    if (lane == 0) atomicAdd(&s_cnt, cnt);
                    __syncthreads();
                    n_ge = s_cnt;
                    __syncthreads();
                    if (tid == 0) s_cnt = 0;
                    __syncthreads();
                    cnt = 0;
                    #pragma unroll
                    for (int j = 0; j < EPT; j++) cnt += ((b[j] << 1) > Tf);
                    #pragma unroll
                    for (int off = 16; off >= 1; off >>= 1)
                        cnt += __shfl_down_sync(FULL, cnt, off);
                    if (lane == 0) atomicAdd(&s_cnt, cnt);
                    __syncthreads();
                    n_gt = s_cnt;
                }
                T    = Tf;
                need = Ku - n_gt;
                geq  = (need == (n_ge - n_gt));
            }
        }

        // ================= APPLY =================
        if (!sel || geq) {
            const bool keepall = (K >= HW);
            float4* __restrict__ yout =
                reinterpret_cast<float4*>(out + (size_t)row * HW);
            #pragma unroll
            for (int j = 0; j < 4; j++) {
                float r[4];
                #pragma unroll
                for (int q = 0; q < 4; q++) {
                    const int idx = j * 4 + q;
                    float xv = __uint_as_float(b[idx]);
                    bool keep = sel ? ((b[idx] << 1) >= T) : keepall;
                    r[q] = keep ? xv : xv * omt;
                }
                yout[tid + 256*j] = make_float4(r[0], r[1], r[2], r[3]);
            }
        } else {
            // rare tie path: exact stable ranks in index order from SMEM
            const uint32_t* bu = &buf[cur][0];
            int myeq = 0;
            #pragma unroll
            for (int j = 0; j < EPT; j++)
                myeq += ((bu[tid*16 + j] << 1) == T);
            uint32_t e = (uint32_t)myeq;
            #pragma unroll
            for (int off = 1; off < 32; off <<= 1) {
                uint32_t v = __shfl_up_sync(FULL, e, off);
                if (lane >= off) e += v;
            }
            if (lane == 31) wtie[wid] = e;
            __syncthreads();
            uint32_t lo = 0;
            #pragma unroll
            for (int w = 0; w < 8; w++) if (w < wid) lo += wtie[w];
            int rank = (int)(e - (uint32_t)myeq + lo);

            const int needi = (int)need;
            float4* __restrict__ yout =
                reinterpret_cast<float4*>(out + (size_t)row * HW);
            #pragma unroll
            for (int i = 0; i < 4; i++) {
                float r[4];
                #pragma unroll
                for (int q = 0; q < 4; q++) {
                    uint32_t bits = bu[tid*16 + i*4 + q];
                    uint32_t key  = bits << 1;
                    bool keep = (key > T) | ((key == T) & (rank < needi));
                    rank += (key == T);
                    float xv = __uint_as_float(bits);
                    r[q] = keep ? xv : xv * omt;
                }
                yout[tid*4 + i] = make_float4(r[0], r[1], r[2], r[3]);
            }
            __syncthreads();   // protect buf[cur] from next iteration's prefetch
        }

        if (!have_next) break;
        cur ^= 1;
        row = nrow;
    }
}

extern "C" void kernel_launch(void* const* d_in, const int* in_sizes, int n_in,
                              void* d_out, int out_size)
{
    const float* x   = (const float*)d_in[0];
    const float* tau = (const float*)d_in[1];
    const int*   k   = (const int*)d_in[2];
    float*       out = (float*)d_out;
    const int    rows = in_sizes[0] / HW;   // n*c = 8192

    const int grid = (rows < GRID) ? rows : GRID;
    topk_blend_kernel<<<grid, THREADS>>>(x, tau, k, out, rows);
}